// round 4
// baseline (speedup 1.0000x reference)
#include <cuda_runtime.h>
#include <math.h>

#define BB 64
#define TT 800
#define EE 1024
#define DD 1024
#define DEDIM 256
#define AA 256
#define VV 8000
#define LL 150
#define KI 1280          // W_ih columns (DE + E)
#define NG 4096          // 4*D

// ---------------- device scratch (static, allocation-free) ----------------
__device__ __align__(128) float g_comp[(size_t)BB * TT * AA];  // 52.4 MB
__device__ __align__(128) float g_h[BB * DD];
__device__ __align__(128) float g_c[BB * DD];
__device__ __align__(128) float g_ctx[BB * EE];
__device__ __align__(128) float g_gp[4 * BB * NG];             // gates split-K partials
__device__ __align__(128) float g_lp[2 * BB * VV];             // logits split-K partials
__device__ __align__(128) float g_attn[BB * TT];
__device__ unsigned g_cnt = 0;
__device__ unsigned g_gen = 0;

struct Params {
    const float *lf, *emb, *W_ih, *W_hh, *b_ih, *b_hh, *phi, *psi, *bpsi, *Wc, *bc;
    const int *state_len, *tokens;
    float* out;
    unsigned nblk;
};

struct SGEM { float As[16][68]; float Bs[16][132]; };
struct SATT { float hs[DD]; float qs[AA]; float en[TT]; float red[256]; };
union Smem { SGEM g; SATT a; };

__device__ __forceinline__ float sigf(float x) { return 1.0f / (1.0f + expf(-x)); }

// ---------------- software grid barrier (co-residency guaranteed by launch) --
__device__ __forceinline__ void gsync(unsigned nblk) {
    __threadfence();                      // release my writes (gpu scope)
    __syncthreads();
    if (threadIdx.x == 0) {
        unsigned gen = *(volatile unsigned*)&g_gen;
        unsigned a = atomicAdd(&g_cnt, 1u);
        if (a == nblk - 1u) {
            g_cnt = 0;
            __threadfence();
            atomicAdd(&g_gen, 1u);
        } else {
            while (*(volatile unsigned*)&g_gen == gen) { __nanosleep(64); }
        }
    }
    __syncthreads();
    __threadfence();                      // acquire: CCTL.IVALL flushes L1D on sm_103a
}

// ---------------- 64x128 fp32 tile compute (4x8 per thread) ------------------
__device__ __forceinline__ void mma16(SGEM& s, float (&acc)[4][8], int tx, int ty) {
#pragma unroll
    for (int kk = 0; kk < 16; kk++) {
        float4 a  = *(const float4*)&s.As[kk][ty * 4];
        float4 b0 = *(const float4*)&s.Bs[kk][tx * 8];
        float4 b1 = *(const float4*)&s.Bs[kk][tx * 8 + 4];
        float av[4] = {a.x, a.y, a.z, a.w};
        float bv[8] = {b0.x, b0.y, b0.z, b0.w, b1.x, b1.y, b1.z, b1.w};
#pragma unroll
        for (int i = 0; i < 4; i++)
#pragma unroll
            for (int j = 0; j < 8; j++) acc[i][j] += av[i] * bv[j];
    }
}

// comp = tanh(lf @ psi + b_psi): M=BB*TT, N=AA, K=EE. 1600 jobs (800 m x 2 n).
__device__ void comp_tile(SGEM& s, const Params& p, int job) {
    int nt = job & 1, mt = job >> 1;
    int m0 = mt * 64, n0 = nt * 128;
    int tid = threadIdx.x, tx = tid & 15, ty = tid >> 4;
    int am = tid >> 2, ak = (tid & 3) * 4;
    int bkk = tid >> 4, bn = (tid & 15) * 8;
    float acc[4][8] = {};
    for (int k0 = 0; k0 < EE; k0 += 16) {
        float4 a4 = *(const float4*)&p.lf[(size_t)(m0 + am) * EE + k0 + ak];
        s.As[ak][am] = a4.x; s.As[ak + 1][am] = a4.y;
        s.As[ak + 2][am] = a4.z; s.As[ak + 3][am] = a4.w;
        const float* wr = p.psi + (size_t)(k0 + bkk) * AA + n0 + bn;
        *(float4*)&s.Bs[bkk][bn]     = *(const float4*)wr;
        *(float4*)&s.Bs[bkk][bn + 4] = *(const float4*)(wr + 4);
        __syncthreads();
        mma16(s, acc, tx, ty);
        __syncthreads();
    }
#pragma unroll
    for (int i = 0; i < 4; i++) {
        int m = m0 + ty * 4 + i;
#pragma unroll
        for (int j = 0; j < 8; j++) {
            int n = n0 + tx * 8 + j;
            g_comp[(size_t)m * AA + n] = tanhf(acc[i][j] + p.bpsi[n]);
        }
    }
}

// gates partials: [emb_t | ctx | h] @ [W_ih | W_hh]^T.  128 jobs = 4 splitK x 32 n-tiles.
__device__ void gates_tile(SGEM& s, const Params& p, int job, int t) {
    int z = job >> 5;
    int nt = job & 31;
    int j0 = nt * 128;
    int tid = threadIdx.x, tx = tid & 15, ty = tid >> 4;
    int am = tid >> 2, ak = (tid & 3) * 4;
    int bj = tid & 127, bk = (tid >> 7) * 8;
    int tok = p.tokens[am * LL + t];
    float acc[4][8] = {};
    int kbeg = z * 576;
    for (int kt = 0; kt < 36; kt++) {
        int k0 = kbeg + kt * 16;
        int k = k0 + ak;
        float4 a4;
        if (k < DEDIM)      a4 = *(const float4*)&p.emb[(size_t)tok * DEDIM + k];
        else if (k < KI)    a4 = *(const float4*)&g_ctx[am * EE + (k - DEDIM)];
        else                a4 = *(const float4*)&g_h[am * DD + (k - KI)];
        s.As[ak][am] = a4.x; s.As[ak + 1][am] = a4.y;
        s.As[ak + 2][am] = a4.z; s.As[ak + 3][am] = a4.w;
        int kc = k0 + bk;
        float4 w0, w1;
        if (kc < KI) {
            const float* r = p.W_ih + (size_t)(j0 + bj) * KI + kc;
            w0 = *(const float4*)r; w1 = *(const float4*)(r + 4);
        } else {
            const float* r = p.W_hh + (size_t)(j0 + bj) * DD + (kc - KI);
            w0 = *(const float4*)r; w1 = *(const float4*)(r + 4);
        }
        s.Bs[bk][bj] = w0.x; s.Bs[bk + 1][bj] = w0.y; s.Bs[bk + 2][bj] = w0.z; s.Bs[bk + 3][bj] = w0.w;
        s.Bs[bk + 4][bj] = w1.x; s.Bs[bk + 5][bj] = w1.y; s.Bs[bk + 6][bj] = w1.z; s.Bs[bk + 7][bj] = w1.w;
        __syncthreads();
        mma16(s, acc, tx, ty);
        __syncthreads();
    }
#pragma unroll
    for (int i = 0; i < 4; i++) {
        int b = ty * 4 + i;
        float* dst = &g_gp[(size_t)(z * BB + b) * NG + j0 + tx * 8];
        *(float4*)dst       = make_float4(acc[i][0], acc[i][1], acc[i][2], acc[i][3]);
        *(float4*)(dst + 4) = make_float4(acc[i][4], acc[i][5], acc[i][6], acc[i][7]);
    }
}

// logits partials: [h | ctx] @ W_cls.  126 jobs = 2 splitK x 63 v-tiles (last partial).
__device__ void logits_tile(SGEM& s, const Params& p, int job) {
    int z = job / 63;
    int nt = job - z * 63;
    int v0 = nt * 128;
    bool full = (nt < 62);
    int tid = threadIdx.x, tx = tid & 15, ty = tid >> 4;
    int am = tid >> 2, ak = (tid & 3) * 4;
    int bkk = tid >> 4, bn = (tid & 15) * 8;
    float acc[4][8] = {};
    int kbeg = z * 1024;
    for (int kt = 0; kt < 64; kt++) {
        int k0 = kbeg + kt * 16;
        int k = k0 + ak;
        float4 a4;
        if (k < DD) a4 = *(const float4*)&g_h[am * DD + k];
        else        a4 = *(const float4*)&g_ctx[am * EE + (k - DD)];
        s.As[ak][am] = a4.x; s.As[ak + 1][am] = a4.y;
        s.As[ak + 2][am] = a4.z; s.As[ak + 3][am] = a4.w;
        const float* wr = p.Wc + (size_t)(k0 + bkk) * VV + v0 + bn;
        if (full) {
            *(float4*)&s.Bs[bkk][bn]     = *(const float4*)wr;
            *(float4*)&s.Bs[bkk][bn + 4] = *(const float4*)(wr + 4);
        } else {
#pragma unroll
            for (int i = 0; i < 8; i++)
                s.Bs[bkk][bn + i] = (v0 + bn + i < VV) ? wr[i] : 0.f;
        }
        __syncthreads();
        mma16(s, acc, tx, ty);
        __syncthreads();
    }
#pragma unroll
    for (int i = 0; i < 4; i++) {
        int b = ty * 4 + i;
        float* dst = &g_lp[(size_t)(z * BB + b) * VV + v0 + tx * 8];
        if (full) {
            *(float4*)dst       = make_float4(acc[i][0], acc[i][1], acc[i][2], acc[i][3]);
            *(float4*)(dst + 4) = make_float4(acc[i][4], acc[i][5], acc[i][6], acc[i][7]);
        } else {
#pragma unroll
            for (int j = 0; j < 8; j++)
                if (v0 + tx * 8 + j < VV) dst[j] = acc[i][j];
        }
    }
}

// q + energy + masked softmax, one block per batch row.
__device__ void attn_phase(SATT& a, const Params& p, int b) {
    int tid = threadIdx.x;
#pragma unroll
    for (int i = 0; i < 4; i++) a.hs[tid + i * 256] = g_h[b * DD + tid + i * 256];
    __syncthreads();
    // q[a] = tanh(sum_k h[k] * phi[k][a])
    {
        float acc0 = 0.f, acc1 = 0.f, acc2 = 0.f, acc3 = 0.f;
        const float* ph = p.phi + tid;
        for (int k = 0; k < DD; k += 4) {
            acc0 += a.hs[k]     * ph[0];
            acc1 += a.hs[k + 1] * ph[AA];
            acc2 += a.hs[k + 2] * ph[2 * AA];
            acc3 += a.hs[k + 3] * ph[3 * AA];
            ph += 4 * AA;
        }
        a.qs[tid] = tanhf((acc0 + acc1) + (acc2 + acc3));
    }
    __syncthreads();
    // energy[t] = 2 * dot(comp[b,t,:], q)
    int w = tid >> 5, lane = tid & 31;
    for (int t = w; t < TT; t += 8) {
        const float* cr = g_comp + ((size_t)b * TT + t) * AA + lane * 8;
        float4 c0 = *(const float4*)cr;
        float4 c1 = *(const float4*)(cr + 4);
        const float* qq = &a.qs[lane * 8];
        float sv = c0.x * qq[0] + c0.y * qq[1] + c0.z * qq[2] + c0.w * qq[3]
                 + c1.x * qq[4] + c1.y * qq[5] + c1.z * qq[6] + c1.w * qq[7];
#pragma unroll
        for (int o = 16; o > 0; o >>= 1) sv += __shfl_down_sync(0xffffffffu, sv, o);
        if (lane == 0) a.en[t] = 2.0f * sv;
    }
    __syncthreads();
    // masked softmax over t < state_len[b]
    int sl = p.state_len[b];
    float m = -1e30f;
    for (int t = tid; t < sl; t += 256) m = fmaxf(m, a.en[t]);
    a.red[tid] = m; __syncthreads();
    for (int o = 128; o > 0; o >>= 1) {
        if (tid < o) a.red[tid] = fmaxf(a.red[tid], a.red[tid + o]);
        __syncthreads();
    }
    m = a.red[0]; __syncthreads();
    float ssum = 0.f;
    for (int t = tid; t < sl; t += 256) { float e = expf(a.en[t] - m); a.en[t] = e; ssum += e; }
    a.red[tid] = ssum; __syncthreads();
    for (int o = 128; o > 0; o >>= 1) {
        if (tid < o) a.red[tid] += a.red[tid + o];
        __syncthreads();
    }
    float inv = 1.0f / a.red[0];
    for (int t = tid; t < TT; t += 256)
        g_attn[b * TT + t] = (t < sl) ? a.en[t] * inv : 0.f;
}

// ctx[b, e] = sum_{t<sl} attn[b,t] * lf[b,t,e].  256 jobs (64 b x 4 e-chunks).
__device__ void ctx_job(SATT& a, const Params& p, int job) {
    int b = job >> 2, ec = job & 3;
    int tid = threadIdx.x;
    int e = ec * 256 + tid;
    int sl = p.state_len[b];
    __syncthreads();
    for (int t = tid; t < TT; t += 256) a.en[t] = g_attn[b * TT + t];
    __syncthreads();
    const float* lfb = p.lf + (size_t)b * TT * EE + e;
    float s0 = 0.f, s1 = 0.f, s2 = 0.f, s3 = 0.f;
    int t = 0;
    for (; t + 4 <= sl; t += 4) {
        s0 += a.en[t]     * lfb[(size_t)t * EE];
        s1 += a.en[t + 1] * lfb[(size_t)(t + 1) * EE];
        s2 += a.en[t + 2] * lfb[(size_t)(t + 2) * EE];
        s3 += a.en[t + 3] * lfb[(size_t)(t + 3) * EE];
    }
    for (; t < sl; t++) s0 += a.en[t] * lfb[(size_t)t * EE];
    g_ctx[b * EE + e] = (s0 + s1) + (s2 + s3);
}

__device__ __forceinline__ void lstm_update(const Params& p, int gid0, int nthr) {
    for (int g = gid0; g < BB * DD; g += nthr) {
        int b = g >> 10, d = g & 1023;
        float gv[4];
#pragma unroll
        for (int q = 0; q < 4; q++) {
            int j = q * DD + d;
            float s = p.b_ih[j] + p.b_hh[j];
#pragma unroll
            for (int z = 0; z < 4; z++) s += g_gp[(size_t)(z * BB + b) * NG + j];
            gv[q] = s;
        }
        float cn = sigf(gv[1]) * g_c[g] + sigf(gv[0]) * tanhf(gv[2]);
        g_c[g] = cn;
        g_h[g] = sigf(gv[3]) * tanhf(cn);
    }
}

__device__ __forceinline__ void logits_reduce(const Params& p, int tt, int gid0, int nthr) {
    for (int i = gid0; i < BB * VV; i += nthr) {
        int b = i / VV, v = i - b * VV;
        p.out[((size_t)b * LL + tt) * VV + v] =
            g_lp[(size_t)b * VV + v] + g_lp[(size_t)(BB + b) * VV + v] + p.bc[v];
    }
}

__global__ void __launch_bounds__(256, 2) decoder_kernel(Params p) {
    __shared__ Smem sm;
    unsigned nblk = p.nblk;
    int tid = threadIdx.x;
    int gid0 = blockIdx.x * 256 + tid;
    int nthr = (int)nblk * 256;

    // phase 0: zero state + encoder projection
    for (int i = gid0; i < BB * DD; i += nthr) { g_h[i] = 0.f; g_c[i] = 0.f; g_ctx[i] = 0.f; }
    for (int job = blockIdx.x; job < 1600; job += nblk) comp_tile(sm.g, p, job);
    gsync(nblk);

    for (int t = 0; t < LL; t++) {
        // A: gates(t) + logits(t-1)
        int njA = 128 + (t > 0 ? 126 : 0);
        for (int job = blockIdx.x; job < njA; job += nblk) {
            if (job < 128) gates_tile(sm.g, p, job, t);
            else           logits_tile(sm.g, p, job - 128);
        }
        gsync(nblk);
        // B: LSTM pointwise + logits reduce
        lstm_update(p, gid0, nthr);
        if (t > 0) logits_reduce(p, t - 1, gid0, nthr);
        gsync(nblk);
        // C: q + energy + softmax (one block per b)
        if (blockIdx.x < BB) attn_phase(sm.a, p, blockIdx.x);
        gsync(nblk);
        // D: context reduction
        for (int job = blockIdx.x; job < 256; job += nblk) ctx_job(sm.a, p, job);
        gsync(nblk);
    }
    // final logits(L-1)
    for (int job = blockIdx.x; job < 126; job += nblk) logits_tile(sm.g, p, job);
    gsync(nblk);
    logits_reduce(p, LL - 1, gid0, nthr);
}

extern "C" void kernel_launch(void* const* d_in, const int* in_sizes, int n_in,
                              void* d_out, int out_size) {
    Params p;
    p.lf        = (const float*)d_in[0];
    p.state_len = (const int*)  d_in[1];
    p.tokens    = (const int*)  d_in[2];
    p.emb       = (const float*)d_in[3];
    p.W_ih      = (const float*)d_in[4];
    p.W_hh      = (const float*)d_in[5];
    p.b_ih      = (const float*)d_in[6];
    p.b_hh      = (const float*)d_in[7];
    p.phi       = (const float*)d_in[8];
    p.psi       = (const float*)d_in[9];
    p.bpsi      = (const float*)d_in[10];
    p.Wc        = (const float*)d_in[11];
    p.bc        = (const float*)d_in[12];
    p.out       = (float*)d_out;

    int dev = 0;
    cudaGetDevice(&dev);
    int sms = 0;
    cudaDeviceGetAttribute(&sms, cudaDevAttrMultiProcessorCount, dev);
    int occ = 0;
    cudaOccupancyMaxActiveBlocksPerMultiprocessor(&occ, decoder_kernel, 256, 0);
    if (occ < 1) occ = 1;
    if (occ > 3) occ = 3;
    unsigned nblk = (unsigned)(sms * occ);
    p.nblk = nblk;

    decoder_kernel<<<nblk, 256>>>(p);
}

// round 5
// speedup vs baseline: 1.4656x; 1.4656x over previous
#include <cuda_runtime.h>
#include <math.h>

#define BB 64
#define TT 800
#define EE 1024
#define DD 1024
#define DEDIM 256
#define AA 256
#define VV 8000
#define LL 150
#define KI 1280          // DE + E
#define NG 4096          // 4*D
#define KC 2048          // D + E
#define GSPLIT 8
#define LSPLIT 4
#define NJ_GATES (GSPLIT * (NG / 128))    // 256 jobs, 18 chunks each
#define NJ_LOGITS (LSPLIT * 63)           // 252 jobs, 32 chunks each
#define NJ_CTX 256
#define NJ_COMP 1600

// ---------------- device scratch (static, allocation-free) ----------------
__device__ __align__(128) float g_comp[(size_t)BB * TT * AA];
__device__ __align__(128) float g_h[2][BB * DD];
__device__ __align__(128) float g_c[BB * DD];
__device__ __align__(128) float g_ctx[2][BB * EE];
__device__ __align__(128) float g_gp[GSPLIT * BB * NG];
__device__ __align__(128) float g_lp[LSPLIT * BB * VV];
__device__ __align__(128) float g_attn[BB * TT];
__device__ unsigned g_cnt = 0;
__device__ unsigned g_gen = 0;
__device__ unsigned g_jq[3] = {0, 0, 0};   // 0: gates/comp, 1: logits, 2: ctx

struct Params {
    const float *lf, *emb, *W_ih, *W_hh, *b_ih, *b_hh, *phi, *psi, *bpsi, *Wc, *bc;
    const int *state_len, *tokens;
    float* out;
    unsigned nblk;
};

struct SGEM { float As[16][68]; float Bs[16][132]; };
struct SATT { float hs[DD]; float qs[AA]; float en[TT]; float red[256]; };
union Smem { SGEM g; SATT a; };

__device__ __forceinline__ float sigf(float x) { return 1.0f / (1.0f + expf(-x)); }

// ---------------- grid barrier; releaser resets selected job counters ------
__device__ __forceinline__ void gsync(unsigned nblk, int rmask) {
    __threadfence();
    __syncthreads();
    if (threadIdx.x == 0) {
        unsigned gen = *(volatile unsigned*)&g_gen;
        if (atomicAdd(&g_cnt, 1u) == nblk - 1u) {
            g_cnt = 0;
            if (rmask & 1) g_jq[0] = 0;
            if (rmask & 2) g_jq[1] = 0;
            if (rmask & 4) g_jq[2] = 0;
            __threadfence();
            atomicAdd(&g_gen, 1u);
        } else {
            while (*(volatile unsigned*)&g_gen == gen) { __nanosleep(64); }
        }
    }
    __syncthreads();
    __threadfence();
}

// ------------- 64x128 tile core: 4 rows x (4+4 split cols) per thread ------
__device__ __forceinline__ void mma16(SGEM& s, float (&acc)[4][8], int tx, int ty) {
#pragma unroll
    for (int kk = 0; kk < 16; kk++) {
        float4 a  = *(const float4*)&s.As[kk][ty * 4];
        float4 b0 = *(const float4*)&s.Bs[kk][tx * 4];
        float4 b1 = *(const float4*)&s.Bs[kk][64 + tx * 4];
        float av[4] = {a.x, a.y, a.z, a.w};
        float bv[8] = {b0.x, b0.y, b0.z, b0.w, b1.x, b1.y, b1.z, b1.w};
#pragma unroll
        for (int i = 0; i < 4; i++)
#pragma unroll
            for (int j = 0; j < 8; j++) acc[i][j] += av[i] * bv[j];
    }
}

// comp = tanh(lf @ psi + b_psi): M=BB*TT, N=AA(2 tiles), K=EE
__device__ void comp_tile(SGEM& s, const Params& p, int job) {
    int nt = job & 1, mt = job >> 1;
    int m0 = mt * 64, n0 = nt * 128;
    int tid = threadIdx.x, tx = tid & 15, ty = tid >> 4;
    int am = tid >> 2, ak = (tid & 3) * 4;
    int bkk = tid >> 4, bn = (tid & 15) * 8;
    float acc[4][8] = {};
    for (int k0 = 0; k0 < EE; k0 += 16) {
        float4 a4 = *(const float4*)&p.lf[(size_t)(m0 + am) * EE + k0 + ak];
        s.As[ak][am] = a4.x; s.As[ak + 1][am] = a4.y;
        s.As[ak + 2][am] = a4.z; s.As[ak + 3][am] = a4.w;
        const float* wr = p.psi + (size_t)(k0 + bkk) * AA + n0 + bn;
        *(float4*)&s.Bs[bkk][bn]     = *(const float4*)wr;
        *(float4*)&s.Bs[bkk][bn + 4] = *(const float4*)(wr + 4);
        __syncthreads();
        mma16(s, acc, tx, ty);
        __syncthreads();
    }
#pragma unroll
    for (int i = 0; i < 4; i++) {
        int m = m0 + ty * 4 + i;
#pragma unroll
        for (int j = 0; j < 8; j++) {
            int n = n0 + ((j < 4) ? (tx * 4 + j) : (64 + tx * 4 + j - 4));
            g_comp[(size_t)m * AA + n] = tanhf(acc[i][j] + p.bpsi[n]);
        }
    }
}

// gates partials: [emb_t | ctx | h] @ [W_ih | W_hh]^T, splitK=8
__device__ void gates_tile(SGEM& s, const Params& p, int job, int t, int pp) {
    int z = job >> 5;
    int nt = job & 31;
    int j0 = nt * 128;
    int tid = threadIdx.x, tx = tid & 15, ty = tid >> 4;
    int am = tid >> 2, ak = (tid & 3) * 4;
    int bj = tid & 127, bk = (tid >> 7) * 8;
    int tok = p.tokens[am * LL + t];
    float acc[4][8] = {};
    int kbeg = z * (2304 / GSPLIT);
    for (int kt = 0; kt < 2304 / GSPLIT / 16; kt++) {
        int k0 = kbeg + kt * 16;
        int k = k0 + ak;
        float4 a4;
        if (k < DEDIM)      a4 = *(const float4*)&p.emb[(size_t)tok * DEDIM + k];
        else if (k < KI)    a4 = *(const float4*)&g_ctx[pp][am * EE + (k - DEDIM)];
        else                a4 = *(const float4*)&g_h[pp][am * DD + (k - KI)];
        s.As[ak][am] = a4.x; s.As[ak + 1][am] = a4.y;
        s.As[ak + 2][am] = a4.z; s.As[ak + 3][am] = a4.w;
        int kc = k0 + bk;
        float4 w0, w1;
        if (kc < KI) {
            const float* r = p.W_ih + (size_t)(j0 + bj) * KI + kc;
            w0 = *(const float4*)r; w1 = *(const float4*)(r + 4);
        } else {
            const float* r = p.W_hh + (size_t)(j0 + bj) * DD + (kc - KI);
            w0 = *(const float4*)r; w1 = *(const float4*)(r + 4);
        }
        s.Bs[bk][bj] = w0.x; s.Bs[bk + 1][bj] = w0.y; s.Bs[bk + 2][bj] = w0.z; s.Bs[bk + 3][bj] = w0.w;
        s.Bs[bk + 4][bj] = w1.x; s.Bs[bk + 5][bj] = w1.y; s.Bs[bk + 6][bj] = w1.z; s.Bs[bk + 7][bj] = w1.w;
        __syncthreads();
        mma16(s, acc, tx, ty);
        __syncthreads();
    }
#pragma unroll
    for (int i = 0; i < 4; i++) {
        int b = ty * 4 + i;
        float* dst = &g_gp[(size_t)(z * BB + b) * NG + j0];
        *(float4*)(dst + tx * 4)      = make_float4(acc[i][0], acc[i][1], acc[i][2], acc[i][3]);
        *(float4*)(dst + 64 + tx * 4) = make_float4(acc[i][4], acc[i][5], acc[i][6], acc[i][7]);
    }
}

// logits partials: [h | ctx] @ W_cls, splitK=4, 63 v-tiles (last half-valid)
__device__ void logits_tile(SGEM& s, const Params& p, int job, int pl) {
    int z = job / 63;
    int nt = job - z * 63;
    int v0 = nt * 128;
    bool full = (nt < 62);
    int tid = threadIdx.x, tx = tid & 15, ty = tid >> 4;
    int am = tid >> 2, ak = (tid & 3) * 4;
    int bkk = tid >> 4, bn = (tid & 15) * 8;
    float acc[4][8] = {};
    int kbeg = z * (KC / LSPLIT);
    for (int kt = 0; kt < KC / LSPLIT / 16; kt++) {
        int k0 = kbeg + kt * 16;
        int k = k0 + ak;
        float4 a4;
        if (k < DD) a4 = *(const float4*)&g_h[pl][am * DD + k];
        else        a4 = *(const float4*)&g_ctx[pl][am * EE + (k - DD)];
        s.As[ak][am] = a4.x; s.As[ak + 1][am] = a4.y;
        s.As[ak + 2][am] = a4.z; s.As[ak + 3][am] = a4.w;
        const float* wr = p.Wc + (size_t)(k0 + bkk) * VV + v0 + bn;
        if (full) {
            *(float4*)&s.Bs[bkk][bn]     = *(const float4*)wr;
            *(float4*)&s.Bs[bkk][bn + 4] = *(const float4*)(wr + 4);
        } else {
#pragma unroll
            for (int i = 0; i < 8; i++)
                s.Bs[bkk][bn + i] = (v0 + bn + i < VV) ? wr[i] : 0.f;
        }
        __syncthreads();
        mma16(s, acc, tx, ty);
        __syncthreads();
    }
#pragma unroll
    for (int i = 0; i < 4; i++) {
        int b = ty * 4 + i;
        float* dst = &g_lp[(size_t)(z * BB + b) * VV + v0];
        *(float4*)(dst + tx * 4) = make_float4(acc[i][0], acc[i][1], acc[i][2], acc[i][3]);
        if (full)
            *(float4*)(dst + 64 + tx * 4) = make_float4(acc[i][4], acc[i][5], acc[i][6], acc[i][7]);
    }
}

// lstm + q + energy + masked softmax for batch row b (one block)
__device__ void lstm_attn(SATT& a, const Params& p, int b, int t) {
    int tid = threadIdx.x;
    int pt = t & 1;
#pragma unroll
    for (int i = 0; i < 4; i++) {
        int d = tid + i * 256;
        int g = b * DD + d;
        float gv[4];
#pragma unroll
        for (int q = 0; q < 4; q++) {
            int j = q * DD + d;
            float s = p.b_ih[j] + p.b_hh[j];
#pragma unroll
            for (int z = 0; z < GSPLIT; z++) s += g_gp[(size_t)(z * BB + b) * NG + j];
            gv[q] = s;
        }
        float cn = sigf(gv[1]) * g_c[g] + sigf(gv[0]) * tanhf(gv[2]);
        g_c[g] = cn;
        float hn = sigf(gv[3]) * tanhf(cn);
        g_h[pt][g] = hn;
        a.hs[d] = hn;
    }
    __syncthreads();
    // q[a] = tanh(sum_k h[k] * phi[k][a]); thread tid -> column tid
    {
        float acc0 = 0.f, acc1 = 0.f, acc2 = 0.f, acc3 = 0.f;
        const float* ph = p.phi + tid;
        for (int k = 0; k < DD; k += 4) {
            acc0 += a.hs[k]     * ph[0];
            acc1 += a.hs[k + 1] * ph[AA];
            acc2 += a.hs[k + 2] * ph[2 * AA];
            acc3 += a.hs[k + 3] * ph[3 * AA];
            ph += 4 * AA;
        }
        a.qs[tid] = tanhf((acc0 + acc1) + (acc2 + acc3));
    }
    __syncthreads();
    // energy, two t in flight per warp
    int w = tid >> 5, lane = tid & 31;
    float4 q0 = *(const float4*)&a.qs[lane * 8];
    float4 q1 = *(const float4*)&a.qs[lane * 8 + 4];
    for (int tb = w; tb < TT; tb += 16) {
        int ta = tb, tc = tb + 8;
        const float* cra = g_comp + ((size_t)b * TT + ta) * AA + lane * 8;
        const float* crc = g_comp + ((size_t)b * TT + tc) * AA + lane * 8;
        float4 x0 = *(const float4*)cra;
        float4 x1 = *(const float4*)(cra + 4);
        float4 y0 = *(const float4*)crc;
        float4 y1 = *(const float4*)(crc + 4);
        float sa = x0.x * q0.x + x0.y * q0.y + x0.z * q0.z + x0.w * q0.w
                 + x1.x * q1.x + x1.y * q1.y + x1.z * q1.z + x1.w * q1.w;
        float sc = y0.x * q0.x + y0.y * q0.y + y0.z * q0.z + y0.w * q0.w
                 + y1.x * q1.x + y1.y * q1.y + y1.z * q1.z + y1.w * q1.w;
#pragma unroll
        for (int o = 16; o > 0; o >>= 1) {
            sa += __shfl_down_sync(0xffffffffu, sa, o);
            sc += __shfl_down_sync(0xffffffffu, sc, o);
        }
        if (lane == 0) { a.en[ta] = 2.0f * sa; a.en[tc] = 2.0f * sc; }
    }
    __syncthreads();
    int sl = p.state_len[b];
    float m = -1e30f;
    for (int tt = tid; tt < sl; tt += 256) m = fmaxf(m, a.en[tt]);
    a.red[tid] = m; __syncthreads();
    for (int o = 128; o > 0; o >>= 1) {
        if (tid < o) a.red[tid] = fmaxf(a.red[tid], a.red[tid + o]);
        __syncthreads();
    }
    m = a.red[0]; __syncthreads();
    float ssum = 0.f;
    for (int tt = tid; tt < sl; tt += 256) { float e = expf(a.en[tt] - m); a.en[tt] = e; ssum += e; }
    a.red[tid] = ssum; __syncthreads();
    for (int o = 128; o > 0; o >>= 1) {
        if (tid < o) a.red[tid] += a.red[tid + o];
        __syncthreads();
    }
    float inv = 1.0f / a.red[0];
    for (int tt = tid; tt < TT; tt += 256)
        g_attn[b * TT + tt] = (tt < sl) ? a.en[tt] * inv : 0.f;
}

// ctx[b, e] = sum_{t<sl} attn[b,t] * lf[b,t,e]
__device__ void ctx_job(SATT& a, const Params& p, int job, int t) {
    int b = job >> 2, ec = job & 3;
    int tid = threadIdx.x;
    int e = ec * 256 + tid;
    int sl = p.state_len[b];
    for (int tt = tid; tt < TT; tt += 256) a.en[tt] = g_attn[b * TT + tt];
    __syncthreads();
    const float* lfb = p.lf + (size_t)b * TT * EE + e;
    float s0 = 0.f, s1 = 0.f, s2 = 0.f, s3 = 0.f;
    int tt = 0;
    for (; tt + 4 <= sl; tt += 4) {
        s0 += a.en[tt]     * lfb[(size_t)tt * EE];
        s1 += a.en[tt + 1] * lfb[(size_t)(tt + 1) * EE];
        s2 += a.en[tt + 2] * lfb[(size_t)(tt + 2) * EE];
        s3 += a.en[tt + 3] * lfb[(size_t)(tt + 3) * EE];
    }
    for (; tt < sl; tt++) s0 += a.en[tt] * lfb[(size_t)tt * EE];
    g_ctx[t & 1][b * EE + e] = (s0 + s1) + (s2 + s3);
}

__device__ __forceinline__ void logits_reduce(const Params& p, int tt, int gid0, int nthr) {
    for (int i = gid0; i < BB * VV; i += nthr) {
        int b = i / VV, v = i - b * VV;
        float s = p.bc[v];
#pragma unroll
        for (int z = 0; z < LSPLIT; z++) s += g_lp[(size_t)(z * BB + b) * VV + v];
        p.out[((size_t)b * LL + tt) * VV + v] = s;
    }
}

// pool helper: pops from g_jq[ci] until >= njobs
#define POOL(ci, njobs, BODY)                                           \
    for (;;) {                                                          \
        __syncthreads();                                                \
        if (threadIdx.x == 0) s_job = (int)atomicAdd(&g_jq[ci], 1u);    \
        __syncthreads();                                                \
        int job = s_job;                                                \
        if (job >= (njobs)) break;                                      \
        BODY;                                                           \
    }

__global__ void __launch_bounds__(256, 2) decoder_kernel(Params p) {
    __shared__ Smem sm;
    __shared__ int s_job;
    const unsigned nblk = p.nblk;
    int tid = threadIdx.x;
    int gid0 = blockIdx.x * 256 + tid;
    int nthr = (int)nblk * 256;

    // phase 0: zero state + encoder projection
    for (int i = gid0; i < BB * DD; i += nthr) {
        g_h[1][i] = 0.f; g_c[i] = 0.f; g_ctx[1][i] = 0.f;
    }
    POOL(0, NJ_COMP, comp_tile(sm.g, p, job))
    gsync(nblk, 1);

    for (int t = 0; t < LL; t++) {
        int pp = (t + 1) & 1;   // parity of step t-1 state
        // A: reduce logits(t-2) + gates(t)
        if (t >= 2) logits_reduce(p, t - 2, gid0, nthr);
        POOL(0, NJ_GATES, gates_tile(sm.g, p, job, t, pp))
        gsync(nblk, 1);
        // BC: lstm+attn (blocks 0..63) overlapped with logits(t-1)
        if (blockIdx.x < BB) lstm_attn(sm.a, p, blockIdx.x, t);
        if (t >= 1) { POOL(1, NJ_LOGITS, logits_tile(sm.g, p, job, pp)) }
        gsync(nblk, 0);
        // D: ctx(t) + leftover logits(t-1)
        POOL(2, NJ_CTX, ctx_job(sm.a, p, job, t))
        if (t >= 1) { POOL(1, NJ_LOGITS, logits_tile(sm.g, p, job, pp)) }
        gsync(nblk, 2 | 4);
    }
    // epilogue: reduce(L-2), compute+reduce logits(L-1)
    logits_reduce(p, LL - 2, gid0, nthr);
    gsync(nblk, 0);
    POOL(1, NJ_LOGITS, logits_tile(sm.g, p, job, (LL - 1) & 1))
    gsync(nblk, 2);
    logits_reduce(p, LL - 1, gid0, nthr);
}

extern "C" void kernel_launch(void* const* d_in, const int* in_sizes, int n_in,
                              void* d_out, int out_size) {
    Params p;
    p.lf        = (const float*)d_in[0];
    p.state_len = (const int*)  d_in[1];
    p.tokens    = (const int*)  d_in[2];
    p.emb       = (const float*)d_in[3];
    p.W_ih      = (const float*)d_in[4];
    p.W_hh      = (const float*)d_in[5];
    p.b_ih      = (const float*)d_in[6];
    p.b_hh      = (const float*)d_in[7];
    p.phi       = (const float*)d_in[8];
    p.psi       = (const float*)d_in[9];
    p.bpsi      = (const float*)d_in[10];
    p.Wc        = (const float*)d_in[11];
    p.bc        = (const float*)d_in[12];
    p.out       = (float*)d_out;

    int dev = 0;
    cudaGetDevice(&dev);
    int sms = 0;
    cudaDeviceGetAttribute(&sms, cudaDevAttrMultiProcessorCount, dev);
    int occ = 0;
    cudaOccupancyMaxActiveBlocksPerMultiprocessor(&occ, decoder_kernel, 256, 0);
    if (occ < 1) occ = 1;
    if (occ > 2) occ = 2;
    unsigned nblk = (unsigned)(sms * occ);
    p.nblk = nblk;

    decoder_kernel<<<nblk, 256>>>(p);
}

// round 7
// speedup vs baseline: 1.8731x; 1.2781x over previous
#include <cuda_runtime.h>
#include <stdint.h>
#include <math.h>

#define BB 64
#define TT 800
#define EE 1024
#define DD 1024
#define DEDIM 256
#define AA 256
#define VV 8000
#define LL 150
#define KI 1280          // DE + E
#define NG 4096          // 4*D
#define KC 2048          // D + E
#define KG 2304          // DE + E + D
#define GSPLIT 16
#define LSPLIT 8
#define GCH (KG / GSPLIT / 16)            // 9 chunks / gates job
#define LCH (KC / LSPLIT / 16)            // 16 chunks / logits job
#define NJ_GATES (GSPLIT * (NG / 128))    // 512
#define NJ_LOGITS (LSPLIT * 63)           // 504
#define NJ_CTX 256
#define NJ_COMP 1600

// ---------------- device scratch (static, allocation-free) ----------------
__device__ __align__(128) float g_comp[(size_t)BB * TT * AA];   // 52.4 MB
__device__ __align__(128) float g_WT[(size_t)KG * NG];          // 37.7 MB k-major gates W
__device__ __align__(128) float g_h[2][BB * DD];
__device__ __align__(128) float g_c[BB * DD];
__device__ __align__(128) float g_ctx[2][BB * EE];
__device__ __align__(128) float g_gp[GSPLIT * BB * NG];
__device__ __align__(128) float g_lp[LSPLIT * BB * VV];
__device__ __align__(128) float g_attn[BB * TT];
__device__ unsigned g_cnt = 0;
__device__ unsigned g_gen = 0;
__device__ unsigned g_jq[3] = {0, 0, 0};

struct Params {
    const float *lf, *emb, *W_ih, *W_hh, *b_ih, *b_hh, *phi, *psi, *bpsi, *Wc, *bc;
    const int *state_len, *tokens;
    float* out;
    unsigned nblk;
};

struct SGEM { float As[2][16][68]; float Bs[2][16][132]; };   // 2 stages
struct SATT { float hs[DD]; float qs[AA]; float en[TT]; float red[256]; };
union Smem { SGEM g; SATT a; };

__device__ __forceinline__ float sigf(float x) { return 1.0f / (1.0f + expf(-x)); }

__device__ __forceinline__ void cp16(uint32_t d, const void* s) {
    asm volatile("cp.async.cg.shared.global [%0], [%1], 16;" :: "r"(d), "l"(s));
}
#define CP_COMMIT() asm volatile("cp.async.commit_group;")
#define CP_WAIT0()  asm volatile("cp.async.wait_group 0;")

// ---------------- grid barrier; releaser resets selected job counters ------
__device__ __forceinline__ void gsync(unsigned nblk, int rmask) {
    __threadfence();
    __syncthreads();
    if (threadIdx.x == 0) {
        unsigned gen = *(volatile unsigned*)&g_gen;
        if (atomicAdd(&g_cnt, 1u) == nblk - 1u) {
            g_cnt = 0;
            if (rmask & 1) g_jq[0] = 0;
            if (rmask & 2) g_jq[1] = 0;
            if (rmask & 4) g_jq[2] = 0;
            __threadfence();
            atomicAdd(&g_gen, 1u);
        } else {
            while (*(volatile unsigned*)&g_gen == gen) { __nanosleep(64); }
        }
    }
    __syncthreads();
    __threadfence();
}

// ------------- 64x128 tile core: 4 rows x (4+4 split cols) per thread ------
__device__ __forceinline__ void mma16(const float (*As)[68], const float (*Bs)[132],
                                      float (&acc)[4][8], int tx, int ty) {
#pragma unroll
    for (int kk = 0; kk < 16; kk++) {
        float4 a  = *(const float4*)&As[kk][ty * 4];
        float4 b0 = *(const float4*)&Bs[kk][tx * 4];
        float4 b1 = *(const float4*)&Bs[kk][64 + tx * 4];
        float av[4] = {a.x, a.y, a.z, a.w};
        float bv[8] = {b0.x, b0.y, b0.z, b0.w, b1.x, b1.y, b1.z, b1.w};
#pragma unroll
        for (int i = 0; i < 4; i++)
#pragma unroll
            for (int j = 0; j < 8; j++) acc[i][j] += av[i] * bv[j];
    }
}

// ================= pipelined tile bodies =================
// A: register-prefetched float4 (transposed into smem); B: cp.async (k-major global).

__device__ __forceinline__ const float* gates_asrc(const Params& p, int pp, int am,
                                                   int tok, int k) {
    if (k < DEDIM) return &p.emb[(size_t)tok * DEDIM + k];
    if (k < KI)    return &g_ctx[pp][am * EE + (k - DEDIM)];
    return &g_h[pp][am * DD + (k - KI)];
}

__device__ void gates_tile(SGEM& s, const Params& p, int job, int t, int pp) {
    int z = job >> 5, nt = job & 31;
    int j0 = nt * 128;
    int kbeg = z * (KG / GSPLIT);
    int tid = threadIdx.x, tx = tid & 15, ty = tid >> 4;
    int am = tid >> 2, akq = (tid & 3) * 4;
    int bk0 = tid >> 5, bn0 = (tid & 31) * 4;
    int tok = p.tokens[am * LL + t];
    uint32_t sB[2] = {
        (uint32_t)__cvta_generic_to_shared(&s.Bs[0][bk0][bn0]),
        (uint32_t)__cvta_generic_to_shared(&s.Bs[1][bk0][bn0]) };
    const size_t brow8 = (size_t)8 * NG;
    float acc[4][8] = {};
    float4 areg;
    {   // prologue: chunk0 A direct + B cp; areg = A(chunk1)
        float4 a0 = *(const float4*)gates_asrc(p, pp, am, tok, kbeg + akq);
        s.As[0][akq + 0][am] = a0.x; s.As[0][akq + 1][am] = a0.y;
        s.As[0][akq + 2][am] = a0.z; s.As[0][akq + 3][am] = a0.w;
        const float* w = &g_WT[(size_t)(kbeg + bk0) * NG + j0 + bn0];
        cp16(sB[0], w);
        cp16(sB[0] + 8 * 132 * 4, w + brow8);
        CP_COMMIT();
        areg = *(const float4*)gates_asrc(p, pp, am, tok, kbeg + 16 + akq);
    }
    for (int kt = 0; kt < GCH; kt++) {
        int cur = kt & 1, nxt = cur ^ 1;
        CP_WAIT0();
        __syncthreads();
        if (kt + 1 < GCH) {
            float* An = &s.As[nxt][0][0];
            An[(akq + 0) * 68 + am] = areg.x; An[(akq + 1) * 68 + am] = areg.y;
            An[(akq + 2) * 68 + am] = areg.z; An[(akq + 3) * 68 + am] = areg.w;
            const float* w = &g_WT[(size_t)(kbeg + (kt + 1) * 16 + bk0) * NG + j0 + bn0];
            cp16(sB[nxt], w);
            cp16(sB[nxt] + 8 * 132 * 4, w + brow8);
        }
        CP_COMMIT();
        if (kt + 2 < GCH)
            areg = *(const float4*)gates_asrc(p, pp, am, tok, kbeg + (kt + 2) * 16 + akq);
        mma16(s.As[cur], s.Bs[cur], acc, tx, ty);
    }
#pragma unroll
    for (int i = 0; i < 4; i++) {
        int b = ty * 4 + i;
        float* dst = &g_gp[(size_t)(z * BB + b) * NG + j0];
        *(float4*)(dst + tx * 4)      = make_float4(acc[i][0], acc[i][1], acc[i][2], acc[i][3]);
        *(float4*)(dst + 64 + tx * 4) = make_float4(acc[i][4], acc[i][5], acc[i][6], acc[i][7]);
    }
}

__device__ void logits_tile(SGEM& s, const Params& p, int job, int pl) {
    int z = job / 63;
    int nt = job - z * 63;
    int v0 = nt * 128;
    bool full = (nt < 62);
    int kbeg = z * (KC / LSPLIT);
    int tid = threadIdx.x, tx = tid & 15, ty = tid >> 4;
    int am = tid >> 2, akq = (tid & 3) * 4;
    int bk0 = tid >> 5, bn0 = (tid & 31) * 4;
    int c0 = v0 + bn0;        if (c0 > VV - 4) c0 = VV - 4;   // clamp: only feeds discarded cols
    uint32_t sB[2] = {
        (uint32_t)__cvta_generic_to_shared(&s.Bs[0][bk0][bn0]),
        (uint32_t)__cvta_generic_to_shared(&s.Bs[1][bk0][bn0]) };
    float acc[4][8] = {};
    const float* hsrc = g_h[pl] + am * DD;
    const float* csrc = g_ctx[pl] + am * EE;
    float4 areg;
    {
        int k = kbeg + akq;
        float4 a0 = (k < DD) ? *(const float4*)&hsrc[k] : *(const float4*)&csrc[k - DD];
        s.As[0][akq + 0][am] = a0.x; s.As[0][akq + 1][am] = a0.y;
        s.As[0][akq + 2][am] = a0.z; s.As[0][akq + 3][am] = a0.w;
        const float* w0 = &p.Wc[(size_t)(kbeg + bk0) * VV];
        cp16(sB[0], w0 + c0);
        cp16(sB[0] + 8 * 132 * 4, w0 + (size_t)8 * VV + c0);
        CP_COMMIT();
        int k1 = kbeg + 16 + akq;
        areg = (k1 < DD) ? *(const float4*)&hsrc[k1] : *(const float4*)&csrc[k1 - DD];
    }
    for (int kt = 0; kt < LCH; kt++) {
        int cur = kt & 1, nxt = cur ^ 1;
        CP_WAIT0();
        __syncthreads();
        if (kt + 1 < LCH) {
            float* An = &s.As[nxt][0][0];
            An[(akq + 0) * 68 + am] = areg.x; An[(akq + 1) * 68 + am] = areg.y;
            An[(akq + 2) * 68 + am] = areg.z; An[(akq + 3) * 68 + am] = areg.w;
            const float* w0 = &p.Wc[(size_t)(kbeg + (kt + 1) * 16 + bk0) * VV];
            cp16(sB[nxt], w0 + c0);
            cp16(sB[nxt] + 8 * 132 * 4, w0 + (size_t)8 * VV + c0);
        }
        CP_COMMIT();
        if (kt + 2 < LCH) {
            int k2 = kbeg + (kt + 2) * 16 + akq;
            areg = (k2 < DD) ? *(const float4*)&hsrc[k2] : *(const float4*)&csrc[k2 - DD];
        }
        mma16(s.As[cur], s.Bs[cur], acc, tx, ty);
    }
#pragma unroll
    for (int i = 0; i < 4; i++) {
        int b = ty * 4 + i;
        float* dst = &g_lp[(size_t)(z * BB + b) * VV + v0];
        *(float4*)(dst + tx * 4) = make_float4(acc[i][0], acc[i][1], acc[i][2], acc[i][3]);
        if (full)
            *(float4*)(dst + 64 + tx * 4) = make_float4(acc[i][4], acc[i][5], acc[i][6], acc[i][7]);
    }
}

__device__ void comp_tile(SGEM& s, const Params& p, int job) {
    int nt = job & 1, mt = job >> 1;
    int m0 = mt * 64, n0 = nt * 128;
    int tid = threadIdx.x, tx = tid & 15, ty = tid >> 4;
    int am = tid >> 2, akq = (tid & 3) * 4;
    int bk0 = tid >> 5, bn0 = (tid & 31) * 4;
    uint32_t sB[2] = {
        (uint32_t)__cvta_generic_to_shared(&s.Bs[0][bk0][bn0]),
        (uint32_t)__cvta_generic_to_shared(&s.Bs[1][bk0][bn0]) };
    const float* arow = p.lf + (size_t)(m0 + am) * EE;
    float acc[4][8] = {};
    float4 areg;
    {
        float4 a0 = *(const float4*)&arow[akq];
        s.As[0][akq + 0][am] = a0.x; s.As[0][akq + 1][am] = a0.y;
        s.As[0][akq + 2][am] = a0.z; s.As[0][akq + 3][am] = a0.w;
        const float* w = &p.psi[(size_t)bk0 * AA + n0 + bn0];
        cp16(sB[0], w);
        cp16(sB[0] + 8 * 132 * 4, w + (size_t)8 * AA);
        CP_COMMIT();
        areg = *(const float4*)&arow[16 + akq];
    }
    for (int kt = 0; kt < EE / 16; kt++) {
        int cur = kt & 1, nxt = cur ^ 1;
        CP_WAIT0();
        __syncthreads();
        if (kt + 1 < EE / 16) {
            float* An = &s.As[nxt][0][0];
            An[(akq + 0) * 68 + am] = areg.x; An[(akq + 1) * 68 + am] = areg.y;
            An[(akq + 2) * 68 + am] = areg.z; An[(akq + 3) * 68 + am] = areg.w;
            const float* w = &p.psi[(size_t)((kt + 1) * 16 + bk0) * AA + n0 + bn0];
            cp16(sB[nxt], w);
            cp16(sB[nxt] + 8 * 132 * 4, w + (size_t)8 * AA);
        }
        CP_COMMIT();
        if (kt + 2 < EE / 16) areg = *(const float4*)&arow[(kt + 2) * 16 + akq];
        mma16(s.As[cur], s.Bs[cur], acc, tx, ty);
    }
#pragma unroll
    for (int i = 0; i < 4; i++) {
        int m = m0 + ty * 4 + i;
#pragma unroll
        for (int j = 0; j < 8; j++) {
            int n = n0 + ((j < 4) ? (tx * 4 + j) : (64 + tx * 4 + j - 4));
            g_comp[(size_t)m * AA + n] = tanhf(acc[i][j] + p.bpsi[n]);
        }
    }
}

// lstm + q + energy + masked softmax for batch row b (one block)
__device__ void lstm_attn(SATT& a, const Params& p, int b, int t) {
    int tid = threadIdx.x;
    int pt = t & 1;
#pragma unroll
    for (int i = 0; i < 4; i++) {
        int d = tid + i * 256;
        int g = b * DD + d;
        float gv[4];
#pragma unroll
        for (int q = 0; q < 4; q++) {
            int j = q * DD + d;
            float s = p.b_ih[j] + p.b_hh[j];
#pragma unroll
            for (int z = 0; z < GSPLIT; z++) s += g_gp[(size_t)(z * BB + b) * NG + j];
            gv[q] = s;
        }
        float cn = sigf(gv[1]) * g_c[g] + sigf(gv[0]) * tanhf(gv[2]);
        g_c[g] = cn;
        float hn = sigf(gv[3]) * tanhf(cn);
        g_h[pt][g] = hn;
        a.hs[d] = hn;
    }
    __syncthreads();
    {
        float acc0 = 0.f, acc1 = 0.f, acc2 = 0.f, acc3 = 0.f;
        const float* ph = p.phi + tid;
        for (int k = 0; k < DD; k += 4) {
            acc0 += a.hs[k]     * ph[0];
            acc1 += a.hs[k + 1] * ph[AA];
            acc2 += a.hs[k + 2] * ph[2 * AA];
            acc3 += a.hs[k + 3] * ph[3 * AA];
            ph += 4 * AA;
        }
        a.qs[tid] = tanhf((acc0 + acc1) + (acc2 + acc3));
    }
    __syncthreads();
    int w = tid >> 5, lane = tid & 31;
    float4 q0 = *(const float4*)&a.qs[lane * 8];
    float4 q1 = *(const float4*)&a.qs[lane * 8 + 4];
    for (int tb = w; tb < TT; tb += 16) {
        int ta = tb, tc = tb + 8;
        const float* cra = g_comp + ((size_t)b * TT + ta) * AA + lane * 8;
        const float* crc = g_comp + ((size_t)b * TT + tc) * AA + lane * 8;
        float4 x0 = *(const float4*)cra;
        float4 x1 = *(const float4*)(cra + 4);
        float4 y0 = *(const float4*)crc;
        float4 y1 = *(const float4*)(crc + 4);
        float sa = x0.x * q0.x + x0.y * q0.y + x0.z * q0.z + x0.w * q0.w
                 + x1.x * q1.x + x1.y * q1.y + x1.z * q1.z + x1.w * q1.w;
        float sc = y0.x * q0.x + y0.y * q0.y + y0.z * q0.z + y0.w * q0.w
                 + y1.x * q1.x + y1.y * q1.y + y1.z * q1.z + y1.w * q1.w;
#pragma unroll
        for (int o = 16; o > 0; o >>= 1) {
            sa += __shfl_down_sync(0xffffffffu, sa, o);
            sc += __shfl_down_sync(0xffffffffu, sc, o);
        }
        if (lane == 0) { a.en[ta] = 2.0f * sa; a.en[tc] = 2.0f * sc; }
    }
    __syncthreads();
    int sl = p.state_len[b];
    float m = -1e30f;
    for (int tt = tid; tt < sl; tt += 256) m = fmaxf(m, a.en[tt]);
    a.red[tid] = m; __syncthreads();
    for (int o = 128; o > 0; o >>= 1) {
        if (tid < o) a.red[tid] = fmaxf(a.red[tid], a.red[tid + o]);
        __syncthreads();
    }
    m = a.red[0]; __syncthreads();
    float ssum = 0.f;
    for (int tt = tid; tt < sl; tt += 256) { float e = expf(a.en[tt] - m); a.en[tt] = e; ssum += e; }
    a.red[tid] = ssum; __syncthreads();
    for (int o = 128; o > 0; o >>= 1) {
        if (tid < o) a.red[tid] += a.red[tid + o];
        __syncthreads();
    }
    float inv = 1.0f / a.red[0];
    for (int tt = tid; tt < TT; tt += 256)
        g_attn[b * TT + tt] = (tt < sl) ? a.en[tt] * inv : 0.f;
}

__device__ void ctx_job(SATT& a, const Params& p, int job, int t) {
    int b = job >> 2, ec = job & 3;
    int tid = threadIdx.x;
    int e = ec * 256 + tid;
    int sl = p.state_len[b];
    for (int tt = tid; tt < TT; tt += 256) a.en[tt] = g_attn[b * TT + tt];
    __syncthreads();
    const float* lfb = p.lf + (size_t)b * TT * EE + e;
    float s0 = 0.f, s1 = 0.f, s2 = 0.f, s3 = 0.f;
    int tt = 0;
    for (; tt + 4 <= sl; tt += 4) {
        s0 += a.en[tt]     * lfb[(size_t)tt * EE];
        s1 += a.en[tt + 1] * lfb[(size_t)(tt + 1) * EE];
        s2 += a.en[tt + 2] * lfb[(size_t)(tt + 2) * EE];
        s3 += a.en[tt + 3] * lfb[(size_t)(tt + 3) * EE];
    }
    for (; tt < sl; tt++) s0 += a.en[tt] * lfb[(size_t)tt * EE];
    g_ctx[t & 1][b * EE + e] = (s0 + s1) + (s2 + s3);
}

__device__ __forceinline__ void logits_reduce(const Params& p, int tt, int gid0, int nthr) {
    for (int i = gid0; i < BB * (VV / 4); i += nthr) {
        int b = i / (VV / 4), v = (i - b * (VV / 4)) * 4;
        float4 s = *(const float4*)&p.bc[v];
#pragma unroll
        for (int z = 0; z < LSPLIT; z++) {
            float4 q = *(const float4*)&g_lp[(size_t)(z * BB + b) * VV + v];
            s.x += q.x; s.y += q.y; s.z += q.z; s.w += q.w;
        }
        *(float4*)&p.out[((size_t)b * LL + tt) * VV + v] = s;
    }
}

#define POOL(ci, njobs, BODY)                                           \
    for (;;) {                                                          \
        __syncthreads();                                                \
        if (threadIdx.x == 0) s_job = (int)atomicAdd(&g_jq[ci], 1u);    \
        __syncthreads();                                                \
        int job = s_job;                                                \
        if (job >= (njobs)) break;                                      \
        BODY;                                                           \
    }

__global__ void __launch_bounds__(256, 2) decoder_kernel(Params p) {
    __shared__ Smem sm;
    __shared__ int s_job;
    const unsigned nblk = p.nblk;
    int tid = threadIdx.x;
    int gid0 = blockIdx.x * 256 + tid;
    int nthr = (int)nblk * 256;

    // phase 0: zero state + transpose gates weights + encoder projection
    for (int i = gid0; i < BB * DD; i += nthr) {
        g_h[1][i] = 0.f; g_c[i] = 0.f; g_ctx[1][i] = 0.f;
    }
    for (size_t i = gid0; i < (size_t)KG * NG; i += (size_t)nthr) {
        int k = (int)(i / NG), j = (int)(i - (size_t)k * NG);
        g_WT[i] = (k < KI) ? p.W_ih[(size_t)j * KI + k]
                           : p.W_hh[(size_t)j * DD + (k - KI)];
    }
    POOL(0, NJ_COMP, comp_tile(sm.g, p, job))
    gsync(nblk, 1);

    for (int t = 0; t < LL; t++) {
        int pp = (t + 1) & 1;
        // A: reduce logits(t-2) + gates(t)
        if (t >= 2) logits_reduce(p, t - 2, gid0, nthr);
        POOL(0, NJ_GATES, gates_tile(sm.g, p, job, t, pp))
        gsync(nblk, 1);
        // BC: lstm+attn (blocks 0..63) overlapped with logits(t-1)
        if (blockIdx.x < BB) lstm_attn(sm.a, p, blockIdx.x, t);
        if (t >= 1) { POOL(1, NJ_LOGITS, logits_tile(sm.g, p, job, pp)) }
        gsync(nblk, 0);
        // D: ctx(t) + leftover logits(t-1)
        POOL(2, NJ_CTX, ctx_job(sm.a, p, job, t))
        if (t >= 1) { POOL(1, NJ_LOGITS, logits_tile(sm.g, p, job, pp)) }
        gsync(nblk, 2 | 4);
    }
    logits_reduce(p, LL - 2, gid0, nthr);
    gsync(nblk, 0);
    POOL(1, NJ_LOGITS, logits_tile(sm.g, p, job, (LL - 1) & 1))
    gsync(nblk, 2);
    logits_reduce(p, LL - 1, gid0, nthr);
}

extern "C" void kernel_launch(void* const* d_in, const int* in_sizes, int n_in,
                              void* d_out, int out_size) {
    Params p;
    p.lf        = (const float*)d_in[0];
    p.state_len = (const int*)  d_in[1];
    p.tokens    = (const int*)  d_in[2];
    p.emb       = (const float*)d_in[3];
    p.W_ih      = (const float*)d_in[4];
    p.W_hh      = (const float*)d_in[5];
    p.b_ih      = (const float*)d_in[6];
    p.b_hh      = (const float*)d_in[7];
    p.phi       = (const float*)d_in[8];
    p.psi       = (const float*)d_in[9];
    p.bpsi      = (const float*)d_in[10];
    p.Wc        = (const float*)d_in[11];
    p.bc        = (const float*)d_in[12];
    p.out       = (float*)d_out;

    int dev = 0;
    cudaGetDevice(&dev);
    int sms = 0;
    cudaDeviceGetAttribute(&sms, cudaDevAttrMultiProcessorCount, dev);
    int occ = 0;
    cudaOccupancyMaxActiveBlocksPerMultiprocessor(&occ, decoder_kernel, 256, 0);
    if (occ < 1) occ = 1;
    if (occ > 2) occ = 2;
    unsigned nblk = (unsigned)(sms * occ);
    p.nblk = nblk;

    decoder_kernel<<<nblk, 256>>>(p);
}